// round 3
// baseline (speedup 1.0000x reference)
#include <cuda_runtime.h>
#include <cuda_bf16.h>
#include <cstdint>
#include <math.h>

#define B_ 64
#define O_ 64
#define I_ 1152
#define D_ 16
#define EPSF 1e-8f

// ---- scratch (device globals; allocation is forbidden) ----
__device__ float g_V[75497472];          // [b][o][i][e]
__device__ float g_ai[B_*I_];            // [b][i]
__device__ float g_aiT[I_*B_];           // [i][b]
__device__ float g_sumai[B_];
__device__ float g_p0s1[72*B_*O_*D_];
__device__ float g_p0s2[72*B_*O_*D_];
__device__ float g_mean[B_*O_*D_];
__device__ float g_i2v[B_*O_*D_];
__device__ float g_coef[B_*O_];
__device__ float g_p1s1[B_*36*O_*D_];
__device__ float g_p1s2[B_*36*O_*D_];
__device__ float g_p1rs[B_*36*O_];

// ================= K1: a_i =================
__global__ __launch_bounds__(256) void k1_ai(const float* __restrict__ u){
    int idx = blockIdx.x*256 + threadIdx.x;
    if (idx >= B_*I_) return;
    const float4* up = ((const float4*)u) + (size_t)idx*4;
    float s = 0.f;
    #pragma unroll
    for (int k=0;k<4;k++){
        float4 v = up[k];
        float x0=v.x+EPSF, x1=v.y+EPSF, x2=v.z+EPSF, x3=v.w+EPSF;
        s += x0*x0+x1*x1+x2*x2+x3*x3;
    }
    float a = sqrtf(s);
    g_ai[idx] = a;
    int b = idx / I_, i = idx % I_;
    g_aiT[i*B_+b] = a;
}

// ================= K1b: per-b sum of a_i =================
__global__ __launch_bounds__(256) void k1b_sum(){
    __shared__ float red[256];
    int b = blockIdx.x;
    float s = 0.f;
    for (int i = threadIdx.x; i < I_; i += 256) s += g_ai[b*I_+i];
    red[threadIdx.x] = s;
    __syncthreads();
    for (int st=128; st>0; st>>=1){
        if (threadIdx.x < st) red[threadIdx.x] += red[threadIdx.x+st];
        __syncthreads();
    }
    if (threadIdx.x == 0) g_sumai[b] = red[0];
}

// ================= K2: votes + iter0 stats =================
// grid (72, 64): 16 i per block, o = blockIdx.y. 256 thr = 64 b x 4 eq.
__global__ __launch_bounds__(256) void k2_votes(const float* __restrict__ u,
                                               const float* __restrict__ W,
                                               const float* __restrict__ bias){
    __shared__ float4 sW[4*16*4];     // [il][e][d4 ^ (e>>2)]
    __shared__ float4 sU[4*64*4];     // [il][b][d4 ^ ((b>>1)&3)]
    __shared__ float  sAi[4*64];
    __shared__ float  sBias[16];
    int t = threadIdx.x;
    int o = blockIdx.y;
    int ibase0 = blockIdx.x * 16;
    int b = t >> 2, eq = t & 3, e0 = eq*4;
    if (t < 16) sBias[t] = bias[o*16+t] + EPSF;

    float s1[4] = {0,0,0,0}, s2[4] = {0,0,0,0};
    const float4* Wp = (const float4*)W;
    const float4* Up = (const float4*)u;

    for (int stage = 0; stage < 4; stage++){
        int ibase = ibase0 + stage*4;
        __syncthreads();
        // stage W: 256 float4 (4 i x 16 e x 4 d4)
        {
            int il = t >> 6, r = t & 63, e = r >> 2, d4 = r & 3;
            int i = ibase + il;
            float4 wv = Wp[((size_t)o*I_ + i)*64 + r];
            sW[(il*16+e)*4 + (d4 ^ (e>>2))] = wv;
        }
        // stage u: 1024 float4 (4 i x 64 b x 4 d4)
        #pragma unroll
        for (int j=0;j<4;j++){
            int idx = t + j*256;
            int il = idx >> 8, r = idx & 255, bb = r >> 2, d4 = r & 3;
            int i = ibase + il;
            float4 uv = Up[((size_t)bb*I_ + i)*4 + d4];
            sU[(il*64+bb)*4 + (d4 ^ ((bb>>1)&3))] = uv;
        }
        {
            int il = t >> 6, bb = t & 63;
            sAi[il*64+bb] = g_aiT[(ibase+il)*B_ + bb];
        }
        __syncthreads();

        #pragma unroll
        for (int il=0; il<4; il++){
            int i = ibase + il;
            float v[4];
            #pragma unroll
            for (int k=0;k<4;k++) v[k] = sBias[e0+k];
            #pragma unroll
            for (int d4=0; d4<4; d4++){
                float4 u4 = sU[(il*64+b)*4 + (d4 ^ ((b>>1)&3))];
                #pragma unroll
                for (int k=0;k<4;k++){
                    float4 w4 = sW[(il*16+e0+k)*4 + (d4 ^ eq)];
                    v[k] += u4.x*w4.x + u4.y*w4.y + u4.z*w4.z + u4.w*w4.w;
                }
            }
            float rra = sAi[il*64+b] * 0.015625f;    // rr = 1/64
            float4 st; st.x=v[0]; st.y=v[1]; st.z=v[2]; st.w=v[3];
            *((float4*)(g_V + (((size_t)b*O_ + o)*I_ + i)*16 + e0)) = st;
            #pragma unroll
            for (int k=0;k<4;k++){
                s1[k] += rra*v[k];
                s2[k] += rra*v[k]*v[k];
            }
        }
    }
    size_t base = (((size_t)blockIdx.x*B_ + b)*O_ + o)*16 + e0;
    float4 a1; a1.x=s1[0]; a1.y=s1[1]; a1.z=s1[2]; a1.w=s1[3];
    float4 a2; a2.x=s2[0]; a2.y=s2[1]; a2.z=s2[2]; a2.w=s2[3];
    *((float4*)(g_p0s1+base)) = a1;
    *((float4*)(g_p0s2+base)) = a2;
}

// ================= K3: iter0 m-step finalize =================
__global__ __launch_bounds__(256) void k3_mstep0(const float* __restrict__ beta_a,
                                                 const float* __restrict__ beta_u){
    int t = threadIdx.x;
    int lane = t & 15;
    int unit = blockIdx.x*16 + (t>>4);
    int b = unit >> 6, o = unit & 63;
    float S1=0.f, S2=0.f;
    for (int tt=0; tt<72; tt++){
        size_t base = (((size_t)tt*B_ + b)*O_ + o)*16 + lane;
        S1 += g_p0s1[base];
        S2 += g_p0s2[base];
    }
    float rs = g_sumai[b] * 0.015625f;
    float inv = 1.f/(rs + EPSF);
    float mean = S1*inv;
    float var  = (S2 - 2.f*mean*S1 + mean*mean*rs)*inv + 1e-4f;
    float lv = logf(var), pv = var;
    #pragma unroll
    for (int k=1;k<16;k<<=1){
        lv += __shfl_xor_sync(0xffffffffu, lv, k, 16);
        pv *= __shfl_xor_sync(0xffffffffu, pv, k, 16);
    }
    float cost = rs*(16.f*beta_u[o] + lv);
    float x = 0.0005f*(beta_a[o]-cost);       // inv_temp iter0 = 0.01*(1-0.95)
    float aj = 1.f/(1.f+expf(-x));
    float p1 = sqrtf(6.283185307179586f*pv + EPSF);
    size_t mb = ((size_t)b*O_+o)*16+lane;
    g_mean[mb] = mean;
    g_i2v[mb]  = 1.f/(2.f*var + EPSF);
    if (lane==0) g_coef[b*O_+o] = aj/(p1+EPSF);
}

// ================= K4: e-step + iter1 partial stats =================
// grid (36, 64): it = blockIdx.x (32 i), b = blockIdx.y. 256 thr = 64 o x 4 eq.
__global__ __launch_bounds__(256) void k4_estep(){
    __shared__ float sMeanT[16*66];
    __shared__ float sI2vT[16*66];
    __shared__ float sCoef[64];
    __shared__ float sAi[32];
    __shared__ float sAP[4][64];
    __shared__ float sRed[4][2];
    __shared__ float sInv[4];
    int t  = threadIdx.x;
    int it = blockIdx.x;
    int b  = blockIdx.y;
    int o  = t >> 2, eq = t & 3;

    for (int idx = t; idx < 1024; idx += 256){
        int oo = idx >> 4, e = idx & 15;
        size_t g = ((size_t)b*O_ + oo)*16 + e;
        sMeanT[e*66+oo] = g_mean[g];
        sI2vT[e*66+oo]  = g_i2v[g];
    }
    if (t < 64) sCoef[t] = g_coef[b*O_+t];
    if (t < 32) sAi[t]   = g_aiT[(it*32+t)*B_ + b];
    __syncthreads();

    float s1[4]={0,0,0,0}, s2[4]={0,0,0,0}, accr=0.f;
    const float4* Vp = (const float4*)(g_V + (((size_t)b*O_ + o)*I_ + it*32)*16 + eq*4);

    for (int g2=0; g2<8; g2++){
        float4 vr[4];
        float  apv[4];
        #pragma unroll
        for (int il=0; il<4; il++){
            int i_loc = g2*4 + il;
            float4 v = Vp[i_loc*4];
            vr[il] = v;
            float vv[4] = {v.x, v.y, v.z, v.w};
            float ss = 0.f;
            #pragma unroll
            for (int k=0;k<4;k++){
                int e = eq*4+k;
                float d = vv[k] - sMeanT[e*66+o];
                ss += d*d*sI2vT[e*66+o];
            }
            ss += __shfl_xor_sync(0xffffffffu, ss, 1);
            ss += __shfl_xor_sync(0xffffffffu, ss, 2);
            apv[il] = sCoef[o]*__expf(-ss);
            if (eq == 0) sAP[il][o] = apv[il];
        }
        __syncthreads();
        {
            int il = t >> 6, o2 = t & 63;
            float v = sAP[il][o2];
            #pragma unroll
            for (int k=1;k<32;k<<=1) v += __shfl_xor_sync(0xffffffffu, v, k);
            if ((t & 31) == 0) sRed[il][(t>>5)&1] = v;
        }
        __syncthreads();
        if (t < 4) sInv[t] = 1.f/(sRed[t][0] + sRed[t][1] + EPSF);
        __syncthreads();
        #pragma unroll
        for (int il=0; il<4; il++){
            float rr  = apv[il]*sInv[il];
            float rra = rr * sAi[g2*4+il];
            float vv[4] = {vr[il].x, vr[il].y, vr[il].z, vr[il].w};
            #pragma unroll
            for (int k=0;k<4;k++){
                s1[k] += rra*vv[k];
                s2[k] += rra*vv[k]*vv[k];
            }
            if (eq == 0) accr += rra;
        }
        __syncthreads();
    }
    size_t base = (((size_t)b*36 + it)*O_ + o)*16 + eq*4;
    float4 a1; a1.x=s1[0]; a1.y=s1[1]; a1.z=s1[2]; a1.w=s1[3];
    float4 a2; a2.x=s2[0]; a2.y=s2[1]; a2.z=s2[2]; a2.w=s2[3];
    *((float4*)(g_p1s1+base)) = a1;
    *((float4*)(g_p1s2+base)) = a2;
    if (eq == 0) g_p1rs[((size_t)b*36 + it)*O_ + o] = accr;
}

// ================= K5: iter1 finalize + output =================
__global__ __launch_bounds__(256) void k5_out(const float* __restrict__ beta_a,
                                              const float* __restrict__ beta_u,
                                              float* __restrict__ out){
    int t = threadIdx.x;
    int lane = t & 15;
    int unit = blockIdx.x*16 + (t>>4);
    int b = unit >> 6, o = unit & 63;
    float S1=0.f, S2=0.f, rs=0.f;
    for (int tt=0; tt<36; tt++){
        size_t base = (((size_t)b*36 + tt)*O_ + o)*16 + lane;
        S1 += g_p1s1[base];
        S2 += g_p1s2[base];
        rs += g_p1rs[((size_t)b*36 + tt)*O_ + o];
    }
    float inv = 1.f/(rs + EPSF);
    float mean = S1*inv;
    float var  = (S2 - 2.f*mean*S1 + mean*mean*rs)*inv + 1e-4f;
    float lv = logf(var);
    float me = mean + EPSF;
    float nn = me*me;
    #pragma unroll
    for (int k=1;k<16;k<<=1){
        lv += __shfl_xor_sync(0xffffffffu, lv, k, 16);
        nn += __shfl_xor_sync(0xffffffffu, nn, k, 16);
    }
    float cost = rs*(16.f*beta_u[o] + lv);
    float x = 0.000975f*(beta_a[o]-cost);     // inv_temp iter1 = 0.01*(1-0.95^2)
    float aj = 1.f/(1.f+expf(-x));
    float nrm = sqrtf(nn);
    out[((size_t)b*O_+o)*16+lane] = aj*mean/(nrm + EPSF);
}

extern "C" void kernel_launch(void* const* d_in, const int* in_sizes, int n_in,
                              void* d_out, int out_size) {
    const float* u      = (const float*)d_in[0];
    const float* W      = (const float*)d_in[1];
    const float* beta_a = (const float*)d_in[2];
    const float* beta_u = (const float*)d_in[3];
    const float* bias   = (const float*)d_in[4];
    float* out = (float*)d_out;

    k1_ai<<<(B_*I_+255)/256, 256>>>(u);
    k1b_sum<<<B_, 256>>>();
    k2_votes<<<dim3(72, 64), 256>>>(u, W, bias);
    k3_mstep0<<<256, 256>>>(beta_a, beta_u);
    k4_estep<<<dim3(36, 64), 256>>>();
    k5_out<<<256, 256>>>(beta_a, beta_u, out);
}